// round 2
// baseline (speedup 1.0000x reference)
#include <cuda_runtime.h>
#include <math.h>
#include <stdint.h>

#define VIEWS 2
#define NV 4000
#define NF 8000
#define NP 2500
#define HH 128
#define WW 128
#define DID 64
#define DEX 72
#define DP 204

#define ZNEAR 0.05f
// BLUR = log(1/1e-4 - 1) * 1e-5 computed in double, cast to float (matches ref)
#define BLUR_F ((float)9.210240366975849e-05)
#define INV_SIGMA 1.0e5f
// clip max = float(1.0 - 1e-7) folded from double, matches JAX weak-type cast
#define CLIPMAX ((float)(1.0 - 1e-7))
#define RPAD 0.0098f   // >= sqrt(BLUR)=0.009597, safety margin

// ---------------- scratch (device globals; no allocations allowed) ----------
__device__ float    g_verts[VIEWS * NV * 3];
__device__ float    g_proj[VIEWS * NV * 2];
__device__ float    g_zv[VIEWS * NV];
__device__ float4   g_frec[VIEWS * NF * 4];
__device__ float4   g_bbox[VIEWS * NF];
__device__ unsigned g_minpt[VIEWS * NP];
__device__ unsigned g_facemin[VIEWS * NF];
__device__ float    g_msk_part[VIEWS * 64];

// output layout: verts (24000) | alpha (32768) | pcl_loss (1) | mask_loss (1)
#define OFF_VERTS 0
#define OFF_ALPHA (VIEWS * NV * 3)
#define OFF_PCL   (OFF_ALPHA + VIEWS * HH * WW)
#define OFF_MASK  (OFF_PCL + 1)

// ---------------- init --------------------------------------------------
__global__ void k_init() {
    int i = blockIdx.x * blockDim.x + threadIdx.x;
    if (i < VIEWS * NP) g_minpt[i] = 0x7f800000u;
    if (i < VIEWS * NF) g_facemin[i] = 0x7f800000u;
}

// ---------------- verts + projection ------------------------------------
__global__ void k_verts(const float* __restrict__ poses,
                        const float* __restrict__ ident,
                        const float* __restrict__ expr,
                        const float* __restrict__ ts,
                        const float* __restrict__ tmpl,
                        const float* __restrict__ sb,
                        const float* __restrict__ eb,
                        const float* __restrict__ pb,
                        const float* __restrict__ fov,
                        float* __restrict__ out_verts) {
    __shared__ float s_id[DID];
    __shared__ float s_ex[DEX];
    __shared__ float s_po[VIEWS * DP];
    int tid = threadIdx.x;
    for (int i = tid; i < DID; i += blockDim.x) s_id[i] = ident[i];
    for (int i = tid; i < DEX; i += blockDim.x) s_ex[i] = expr[i];
    for (int i = tid; i < VIEWS * DP; i += blockDim.x) s_po[i] = poses[i];
    __syncthreads();

    int v = blockIdx.x * blockDim.x + tid;
    if (v >= NV) return;

    float bx = tmpl[3 * v], by = tmpl[3 * v + 1], bz = tmpl[3 * v + 2];
    for (int i = 0; i < DID; i++) {
        float c = s_id[i];
        const float* p = sb + (size_t)i * (NV * 3) + 3 * v;
        bx += c * p[0]; by += c * p[1]; bz += c * p[2];
    }
    for (int i = 0; i < DEX; i++) {
        float c = s_ex[i];
        const float* p = eb + (size_t)i * (NV * 3) + 3 * v;
        bx += c * p[0]; by += c * p[1]; bz += c * p[2];
    }
    float p0x = 0.f, p0y = 0.f, p0z = 0.f;
    float p1x = 0.f, p1y = 0.f, p1z = 0.f;
    for (int i = 0; i < DP; i++) {
        const float* p = pb + (size_t)i * (NV * 3) + 3 * v;
        float px = p[0], py = p[1], pz = p[2];
        float c0 = s_po[i], c1 = s_po[DP + i];
        p0x += c0 * px; p0y += c0 * py; p0z += c0 * pz;
        p1x += c1 * px; p1y += c1 * py; p1z += c1 * pz;
    }
    for (int k = 0; k < VIEWS; k++) {
        float rx = bx + (k ? p1x : p0x);
        float ry = by + (k ? p1y : p0y);
        float rz = bz + (k ? p1z : p0z);
        float wx = rx / 100.0f + ts[3 * k + 0];
        float wy = -(ry / 100.0f) + ts[3 * k + 1];
        float wz = -(rz / 100.0f) + ts[3 * k + 2];
        int o = (k * NV + v) * 3;
        out_verts[OFF_VERTS + o + 0] = wx;
        out_verts[OFF_VERTS + o + 1] = wy;
        out_verts[OFF_VERTS + o + 2] = wz;
        g_verts[o + 0] = wx; g_verts[o + 1] = wy; g_verts[o + 2] = wz;
        // camera: v_cam = verts * (-1,-1,1)
        float s = 1.0f / tanf(fov[k] * (float)(3.14159265358979323846 / 180.0) * 0.5f);
        float zden = fmaxf(wz, 1e-6f);
        g_proj[(k * NV + v) * 2 + 0] = s * (-wx) / zden;
        g_proj[(k * NV + v) * 2 + 1] = s * (-wy) / zden;
        g_zv[k * NV + v] = wz;
    }
}

// ---------------- per-face 2D records + bboxes ---------------------------
__global__ void k_faceprep(const int* __restrict__ faces) {
    int idx = blockIdx.x * blockDim.x + threadIdx.x;
    if (idx >= VIEWS * NF) return;
    int k = idx / NF, f = idx % NF;
    int i0 = faces[3 * f], i1 = faces[3 * f + 1], i2 = faces[3 * f + 2];
    float ax = g_proj[(k * NV + i0) * 2], ay = g_proj[(k * NV + i0) * 2 + 1];
    float bx = g_proj[(k * NV + i1) * 2], by = g_proj[(k * NV + i1) * 2 + 1];
    float cx = g_proj[(k * NV + i2) * 2], cy = g_proj[(k * NV + i2) * 2 + 1];
    float z0 = g_zv[k * NV + i0], z1 = g_zv[k * NV + i1], z2 = g_zv[k * NV + i2];
    bool valid = (z0 > ZNEAR) && (z1 > ZNEAR) && (z2 > ZNEAR);
    float e1x = bx - ax, e1y = by - ay;
    float e2x = cx - bx, e2y = cy - by;
    float e3x = ax - cx, e3y = ay - cy;
    float inv1 = 1.0f / fmaxf(e1x * e1x + e1y * e1y, 1e-12f);
    float inv2 = 1.0f / fmaxf(e2x * e2x + e2y * e2y, 1e-12f);
    float inv3 = 1.0f / fmaxf(e3x * e3x + e3y * e3y, 1e-12f);
    float bminx = fminf(ax, fminf(bx, cx)), bmaxx = fmaxf(ax, fmaxf(bx, cx));
    float bminy = fminf(ay, fminf(by, cy)), bmaxy = fmaxf(ay, fmaxf(by, cy));
    if (!valid) { bminx = bminy = 1e30f; bmaxx = bmaxy = -1e30f; }
    g_frec[idx * 4 + 0] = make_float4(ax, ay, bx, by);
    g_frec[idx * 4 + 1] = make_float4(cx, cy, e1x, e1y);
    g_frec[idx * 4 + 2] = make_float4(e2x, e2y, e3x, e3y);
    g_frec[idx * 4 + 3] = make_float4(inv1, inv2, inv3, 0.f);
    g_bbox[idx] = make_float4(bminx, bminy, bmaxx, bmaxy);
}

// ---------------- 3D point-triangle squared distance (matches reference) --
__device__ __forceinline__ float clamp01(float t) {
    return fminf(fmaxf(t, 0.0f), 1.0f);
}

__device__ __forceinline__ float ptri_sqdist(
    float px, float py, float pz,
    float ax, float ay, float az,
    float bx, float by, float bz,
    float cx, float cy, float cz) {
    const float eps = 1e-12f;
    float abx = bx - ax, aby = by - ay, abz = bz - az;
    float acx = cx - ax, acy = cy - ay, acz = cz - az;
    float apx = px - ax, apy = py - ay, apz = pz - az;
    float d1 = abx * apx + aby * apy + abz * apz;
    float d2 = acx * apx + acy * apy + acz * apz;
    float bpx = px - bx, bpy = py - by, bpz = pz - bz;
    float d3 = abx * bpx + aby * bpy + abz * bpz;
    float d4 = acx * bpx + acy * bpy + acz * bpz;
    float cpx = px - cx, cpy = py - cy, cpz = pz - cz;
    float d5 = abx * cpx + aby * cpy + abz * cpz;
    float d6 = acx * cpx + acy * cpy + acz * cpz;
    float va = d3 * d6 - d5 * d4;
    float vb = d5 * d2 - d1 * d6;
    float vc = d1 * d4 - d3 * d2;
    float den = va + vb + vc;
    den = (fabsf(den) > eps) ? den : 1.0f;
    float wb = vb / den, wc = vc / den;
    float clx = ax + abx * wb + acx * wc;
    float cly = ay + aby * wb + acy * wc;
    float clz = az + abz * wb + acz * wc;
    float tabden = (fabsf(d1 - d3) > eps) ? (d1 - d3) : 1.0f;
    float tab = clamp01(d1 / tabden);
    float tacden = (fabsf(d2 - d6) > eps) ? (d2 - d6) : 1.0f;
    float tac = clamp01(d2 / tacden);
    float numbc = d4 - d3;
    float denbc = numbc + (d5 - d6);
    denbc = (fabsf(denbc) > eps) ? denbc : 1.0f;
    float tbc = clamp01(numbc / denbc);
    if (va <= 0.f && numbc >= 0.f && (d5 - d6) >= 0.f) {
        clx = bx + (cx - bx) * tbc; cly = by + (cy - by) * tbc; clz = bz + (cz - bz) * tbc;
    }
    if (vb <= 0.f && d2 >= 0.f && d6 <= 0.f) {
        clx = ax + acx * tac; cly = ay + acy * tac; clz = az + acz * tac;
    }
    if (vc <= 0.f && d1 >= 0.f && d3 <= 0.f) {
        clx = ax + abx * tab; cly = ay + aby * tab; clz = az + abz * tab;
    }
    if (d6 >= 0.f && d5 <= d6) { clx = cx; cly = cy; clz = cz; }
    if (d3 >= 0.f && d4 <= d3) { clx = bx; cly = by; clz = bz; }
    if (d1 <= 0.f && d2 <= 0.f) { clx = ax; cly = ay; clz = az; }
    float dx = px - clx, dy = py - cly, dz = pz - clz;
    return dx * dx + dy * dy + dz * dz;
}

// ---------------- pcl: dual min-reduction over 2500x8000 ------------------
#define FT 128
#define PT 625
__global__ void __launch_bounds__(FT) k_pcl(const int* __restrict__ faces,
                                            const float* __restrict__ points) {
    int view = blockIdx.z;
    int f = blockIdx.x * FT + threadIdx.x;
    int p0 = blockIdx.y * PT;
    int tid = threadIdx.x, lane = tid & 31, warp = tid >> 5;
    __shared__ float s_wmin[4][PT];

    float ax, ay, az, bx, by, bz, cx, cy, cz;
    {
        int ff = (f < NF) ? f : 0;
        int i0 = __ldg(&faces[3 * ff]);
        int i1 = __ldg(&faces[3 * ff + 1]);
        int i2 = __ldg(&faces[3 * ff + 2]);
        const float* vb = g_verts + view * NV * 3;
        ax = vb[3 * i0]; ay = vb[3 * i0 + 1]; az = vb[3 * i0 + 2];
        bx = vb[3 * i1]; by = vb[3 * i1 + 1]; bz = vb[3 * i1 + 2];
        cx = vb[3 * i2]; cy = vb[3 * i2 + 1]; cz = vb[3 * i2 + 2];
    }
    float fm = 1e30f;
    const float* pp = points + (size_t)(view * NP + p0) * 3;
    for (int i = 0; i < PT; i++) {
        float px = __ldg(&pp[3 * i]);
        float py = __ldg(&pp[3 * i + 1]);
        float pz = __ldg(&pp[3 * i + 2]);
        float d = ptri_sqdist(px, py, pz, ax, ay, az, bx, by, bz, cx, cy, cz);
        if (f >= NF) d = 1e30f; else fm = fminf(fm, d);
        float m = d;
        #pragma unroll
        for (int o = 16; o; o >>= 1) m = fminf(m, __shfl_xor_sync(0xffffffffu, m, o));
        if (lane == 0) s_wmin[warp][i] = m;
    }
    __syncthreads();
    for (int i = tid; i < PT; i += FT) {
        float m = fminf(fminf(s_wmin[0][i], s_wmin[1][i]),
                        fminf(s_wmin[2][i], s_wmin[3][i]));
        atomicMin(&g_minpt[view * NP + p0 + i], __float_as_uint(m));
    }
    if (f < NF) atomicMin(&g_facemin[view * NF + f], __float_as_uint(fm));
}

// ---------------- raster: tiled, bbox-culled soft rasterization ----------
__global__ void __launch_bounds__(256) k_raster(const float* __restrict__ masks,
                                                float* __restrict__ out) {
    int view = blockIdx.y;
    int tile = blockIdx.x;                 // 0..63 (8x8 grid of 16x16 tiles)
    int tx0 = (tile & 7) * 16, ty0 = (tile >> 3) * 16;
    int tid = threadIdx.x;
    int px = tx0 + (tid & 15), py = ty0 + (tid >> 4);
    float qx = 1.0f - (2.0f * px + 1.0f) / 128.0f;
    float qy = 1.0f - (2.0f * py + 1.0f) / 128.0f;
    // pixel-center rect of this tile (x decreasing with column index)
    float tminx = 1.0f - (2.0f * (tx0 + 15) + 1.0f) / 128.0f;
    float tmaxx = 1.0f - (2.0f * tx0 + 1.0f) / 128.0f;
    float tminy = 1.0f - (2.0f * (ty0 + 15) + 1.0f) / 128.0f;
    float tmaxy = 1.0f - (2.0f * ty0 + 1.0f) / 128.0f;

    __shared__ int s_list[256];
    __shared__ int s_wc[8];
    __shared__ int s_woff[8];
    __shared__ int s_tot;

    const float4* bb_base = g_bbox + view * NF;
    const float4* fr_base = g_frec + (size_t)view * NF * 4;
    int lane = tid & 31, warp = tid >> 5;
    float acc = 0.0f;

    for (int base = 0; base < NF; base += 256) {
        int f = base + tid;
        bool ov = false;
        if (f < NF) {
            float4 bb = __ldg(&bb_base[f]);
            ov = (bb.x - RPAD <= tmaxx) && (bb.z + RPAD >= tminx) &&
                 (bb.y - RPAD <= tmaxy) && (bb.w + RPAD >= tminy);
        }
        unsigned bal = __ballot_sync(0xffffffffu, ov);
        if (lane == 0) s_wc[warp] = __popc(bal);
        __syncthreads();
        if (tid == 0) {
            int s = 0;
            for (int w = 0; w < 8; w++) { s_woff[w] = s; s += s_wc[w]; }
            s_tot = s;
        }
        __syncthreads();
        if (ov) {
            int pos = s_woff[warp] + __popc(bal & ((1u << lane) - 1u));
            s_list[pos] = f;
        }
        __syncthreads();
        int M = s_tot;
        for (int j = 0; j < M; j++) {
            int fi = s_list[j];
            float4 r0 = __ldg(&fr_base[fi * 4 + 0]);
            float4 r1 = __ldg(&fr_base[fi * 4 + 1]);
            float4 r2 = __ldg(&fr_base[fi * 4 + 2]);
            float4 r3 = __ldg(&fr_base[fi * 4 + 3]);
            float pax = qx - r0.x, pay = qy - r0.y;
            float pbx = qx - r0.z, pby = qy - r0.w;
            float pcx = qx - r1.x, pcy = qy - r1.y;
            float e1x = r1.z, e1y = r1.w;
            float e2x = r2.x, e2y = r2.y;
            float e3x = r2.z, e3y = r2.w;
            float t1 = clamp01((pax * e1x + pay * e1y) * r3.x);
            float dx = pax - t1 * e1x, dy = pay - t1 * e1y;
            float dd = dx * dx + dy * dy;
            float t2 = clamp01((pbx * e2x + pby * e2y) * r3.y);
            dx = pbx - t2 * e2x; dy = pby - t2 * e2y;
            dd = fminf(dd, dx * dx + dy * dy);
            float t3 = clamp01((pcx * e3x + pcy * e3y) * r3.z);
            dx = pcx - t3 * e3x; dy = pcy - t3 * e3y;
            dd = fminf(dd, dx * dx + dy * dy);
            float s1 = e1x * pay - e1y * pax;
            float s2 = e2x * pby - e2y * pbx;
            float s3 = e3x * pcy - e3y * pcx;
            bool inside = (s1 >= 0.f && s2 >= 0.f && s3 >= 0.f) ||
                          (s1 <= 0.f && s2 <= 0.f && s3 <= 0.f);
            float d = inside ? -dd : dd;
            if (d < BLUR_F) {
                float ex = expf(d * INV_SIGMA);
                float prob = 1.0f / (1.0f + ex);
                prob = fminf(prob, CLIPMAX);
                acc += log1pf(-prob);
            }
        }
        __syncthreads();
    }

    float alpha = 1.0f - expf(acc);
    int pix = py * WW + px;
    out[OFF_ALPHA + view * HH * WW + pix] = alpha;
    float m = masks[view * HH * WW + pix];
    float diff = alpha - m;
    __shared__ float s_red[256];
    s_red[tid] = diff * diff;
    __syncthreads();
    for (int s = 128; s > 0; s >>= 1) {
        if (tid < s) s_red[tid] += s_red[tid + s];
        __syncthreads();
    }
    if (tid == 0) g_msk_part[view * 64 + tile] = s_red[0];
}

// ---------------- final deterministic reductions -------------------------
__global__ void __launch_bounds__(256) k_final(float* __restrict__ out) {
    __shared__ float s[256];
    int tid = threadIdx.x;

    float a = 0.f;
    for (int i = tid; i < VIEWS * NP; i += 256) a += __uint_as_float(g_minpt[i]);
    s[tid] = a; __syncthreads();
    for (int st = 128; st > 0; st >>= 1) { if (tid < st) s[tid] += s[tid + st]; __syncthreads(); }
    float summin = s[0]; __syncthreads();

    float b = 0.f;
    for (int i = tid; i < VIEWS * NF; i += 256) b += __uint_as_float(g_facemin[i]);
    s[tid] = b; __syncthreads();
    for (int st = 128; st > 0; st >>= 1) { if (tid < st) s[tid] += s[tid + st]; __syncthreads(); }
    float sumface = s[0]; __syncthreads();

    float c = 0.f;
    for (int i = tid; i < VIEWS * 64; i += 256) c += g_msk_part[i];
    s[tid] = c; __syncthreads();
    for (int st = 128; st > 0; st >>= 1) { if (tid < st) s[tid] += s[tid + st]; __syncthreads(); }
    float sumsse = s[0];

    if (tid == 0) {
        out[OFF_PCL] = summin / (float)(VIEWS * NP) + sumface / (float)(VIEWS * NF);
        out[OFF_MASK] = sumsse / (float)(VIEWS * HH * WW);
    }
}

// ---------------- launch -------------------------------------------------
extern "C" void kernel_launch(void* const* d_in, const int* in_sizes, int n_in,
                              void* d_out, int out_size) {
    const float* poses = (const float*)d_in[0];
    const float* ident = (const float*)d_in[1];
    const float* expr  = (const float*)d_in[2];
    const float* ts    = (const float*)d_in[3];
    const float* points = (const float*)d_in[4];
    const float* masks  = (const float*)d_in[5];
    const float* tmpl   = (const float*)d_in[6];
    const float* sb     = (const float*)d_in[7];
    const float* eb     = (const float*)d_in[8];
    const float* pb     = (const float*)d_in[9];
    const int*   faces  = (const int*)d_in[10];
    const float* fov    = (const float*)d_in[11];
    float* out = (float*)d_out;

    k_init<<<(VIEWS * NF + 255) / 256, 256>>>();
    k_verts<<<(NV + 127) / 128, 128>>>(poses, ident, expr, ts, tmpl, sb, eb, pb, fov, out);
    k_faceprep<<<(VIEWS * NF + 255) / 256, 256>>>(faces);
    {
        dim3 grid((NF + FT - 1) / FT, NP / PT, VIEWS);
        k_pcl<<<grid, FT>>>(faces, points);
    }
    {
        dim3 grid(64, VIEWS);
        k_raster<<<grid, 256>>>(masks, out);
    }
    k_final<<<1, 256>>>(out);
}

// round 3
// speedup vs baseline: 1.0050x; 1.0050x over previous
#include <cuda_runtime.h>
#include <math.h>
#include <stdint.h>

#define VIEWS 2
#define NV 4000
#define NF 8000
#define NP 2500
#define HH 128
#define WW 128
#define DID 64
#define DEX 72
#define DP 204

#define ZNEAR 0.05f
// BLUR = log(1/1e-4 - 1) * 1e-5 computed in double, cast to float (matches ref)
#define BLUR_F ((float)9.210240366975849e-05)
#define INV_SIGMA 1.0e5f
// clip max = float(1.0 - 1e-7) folded from double, matches JAX weak-type cast
#define CLIPMAX ((float)(1.0 - 1e-7))
#define RPAD 0.0098f   // >= sqrt(BLUR)=0.009597, safety margin

// ---------------- scratch (device globals; no allocations allowed) ----------
__device__ float    g_verts[VIEWS * NV * 3];
__device__ float    g_proj[VIEWS * NV * 2];
__device__ float    g_zv[VIEWS * NV];
__device__ float4   g_frec[VIEWS * NF * 4];
__device__ float4   g_bbox[VIEWS * NF];
__device__ unsigned g_minpt[VIEWS * NP];
__device__ unsigned g_facemin[VIEWS * NF];
__device__ float    g_msk_part[VIEWS * 64];

// output layout: verts (24000) | alpha (32768) | pcl_loss (1) | mask_loss (1)
#define OFF_VERTS 0
#define OFF_ALPHA (VIEWS * NV * 3)
#define OFF_PCL   (OFF_ALPHA + VIEWS * HH * WW)
#define OFF_MASK  (OFF_PCL + 1)

// ---------------- init --------------------------------------------------
__global__ void k_init() {
    int i = blockIdx.x * blockDim.x + threadIdx.x;
    if (i < VIEWS * NP) g_minpt[i] = 0x7f800000u;
    if (i < VIEWS * NF) g_facemin[i] = 0x7f800000u;
}

// ---------------- verts + projection ------------------------------------
__global__ void k_verts(const float* __restrict__ poses,
                        const float* __restrict__ ident,
                        const float* __restrict__ expr,
                        const float* __restrict__ ts,
                        const float* __restrict__ tmpl,
                        const float* __restrict__ sb,
                        const float* __restrict__ eb,
                        const float* __restrict__ pb,
                        const float* __restrict__ fov,
                        float* __restrict__ out_verts) {
    __shared__ float s_id[DID];
    __shared__ float s_ex[DEX];
    __shared__ float s_po[VIEWS * DP];
    int tid = threadIdx.x;
    for (int i = tid; i < DID; i += blockDim.x) s_id[i] = ident[i];
    for (int i = tid; i < DEX; i += blockDim.x) s_ex[i] = expr[i];
    for (int i = tid; i < VIEWS * DP; i += blockDim.x) s_po[i] = poses[i];
    __syncthreads();

    int v = blockIdx.x * blockDim.x + tid;
    if (v >= NV) return;

    float bx = tmpl[3 * v], by = tmpl[3 * v + 1], bz = tmpl[3 * v + 2];
    for (int i = 0; i < DID; i++) {
        float c = s_id[i];
        const float* p = sb + (size_t)i * (NV * 3) + 3 * v;
        bx += c * p[0]; by += c * p[1]; bz += c * p[2];
    }
    for (int i = 0; i < DEX; i++) {
        float c = s_ex[i];
        const float* p = eb + (size_t)i * (NV * 3) + 3 * v;
        bx += c * p[0]; by += c * p[1]; bz += c * p[2];
    }
    float p0x = 0.f, p0y = 0.f, p0z = 0.f;
    float p1x = 0.f, p1y = 0.f, p1z = 0.f;
    for (int i = 0; i < DP; i++) {
        const float* p = pb + (size_t)i * (NV * 3) + 3 * v;
        float px = p[0], py = p[1], pz = p[2];
        float c0 = s_po[i], c1 = s_po[DP + i];
        p0x += c0 * px; p0y += c0 * py; p0z += c0 * pz;
        p1x += c1 * px; p1y += c1 * py; p1z += c1 * pz;
    }
    for (int k = 0; k < VIEWS; k++) {
        float rx = bx + (k ? p1x : p0x);
        float ry = by + (k ? p1y : p0y);
        float rz = bz + (k ? p1z : p0z);
        float wx = rx / 100.0f + ts[3 * k + 0];
        float wy = -(ry / 100.0f) + ts[3 * k + 1];
        float wz = -(rz / 100.0f) + ts[3 * k + 2];
        int o = (k * NV + v) * 3;
        out_verts[OFF_VERTS + o + 0] = wx;
        out_verts[OFF_VERTS + o + 1] = wy;
        out_verts[OFF_VERTS + o + 2] = wz;
        g_verts[o + 0] = wx; g_verts[o + 1] = wy; g_verts[o + 2] = wz;
        // camera: v_cam = verts * (-1,-1,1)
        float s = 1.0f / tanf(fov[k] * (float)(3.14159265358979323846 / 180.0) * 0.5f);
        float zden = fmaxf(wz, 1e-6f);
        g_proj[(k * NV + v) * 2 + 0] = s * (-wx) / zden;
        g_proj[(k * NV + v) * 2 + 1] = s * (-wy) / zden;
        g_zv[k * NV + v] = wz;
    }
}

// ---------------- per-face 2D records + bboxes ---------------------------
__global__ void k_faceprep(const int* __restrict__ faces) {
    int idx = blockIdx.x * blockDim.x + threadIdx.x;
    if (idx >= VIEWS * NF) return;
    int k = idx / NF, f = idx % NF;
    int i0 = faces[3 * f], i1 = faces[3 * f + 1], i2 = faces[3 * f + 2];
    float ax = g_proj[(k * NV + i0) * 2], ay = g_proj[(k * NV + i0) * 2 + 1];
    float bx = g_proj[(k * NV + i1) * 2], by = g_proj[(k * NV + i1) * 2 + 1];
    float cx = g_proj[(k * NV + i2) * 2], cy = g_proj[(k * NV + i2) * 2 + 1];
    float z0 = g_zv[k * NV + i0], z1 = g_zv[k * NV + i1], z2 = g_zv[k * NV + i2];
    bool valid = (z0 > ZNEAR) && (z1 > ZNEAR) && (z2 > ZNEAR);
    float e1x = bx - ax, e1y = by - ay;
    float e2x = cx - bx, e2y = cy - by;
    float e3x = ax - cx, e3y = ay - cy;
    float inv1 = 1.0f / fmaxf(e1x * e1x + e1y * e1y, 1e-12f);
    float inv2 = 1.0f / fmaxf(e2x * e2x + e2y * e2y, 1e-12f);
    float inv3 = 1.0f / fmaxf(e3x * e3x + e3y * e3y, 1e-12f);
    float bminx = fminf(ax, fminf(bx, cx)), bmaxx = fmaxf(ax, fmaxf(bx, cx));
    float bminy = fminf(ay, fminf(by, cy)), bmaxy = fmaxf(ay, fmaxf(by, cy));
    if (!valid) { bminx = bminy = 1e30f; bmaxx = bmaxy = -1e30f; }
    g_frec[idx * 4 + 0] = make_float4(ax, ay, bx, by);
    g_frec[idx * 4 + 1] = make_float4(cx, cy, e1x, e1y);
    g_frec[idx * 4 + 2] = make_float4(e2x, e2y, e3x, e3y);
    g_frec[idx * 4 + 3] = make_float4(inv1, inv2, inv3, 0.f);
    g_bbox[idx] = make_float4(bminx, bminy, bmaxx, bmaxy);
}

// ---------------- 3D point-triangle squared distance (matches reference) --
__device__ __forceinline__ float clamp01(float t) {
    return fminf(fmaxf(t, 0.0f), 1.0f);
}

__device__ __forceinline__ float ptri_sqdist(
    float px, float py, float pz,
    float ax, float ay, float az,
    float bx, float by, float bz,
    float cx, float cy, float cz) {
    const float eps = 1e-12f;
    float abx = bx - ax, aby = by - ay, abz = bz - az;
    float acx = cx - ax, acy = cy - ay, acz = cz - az;
    float apx = px - ax, apy = py - ay, apz = pz - az;
    float d1 = abx * apx + aby * apy + abz * apz;
    float d2 = acx * apx + acy * apy + acz * apz;
    float bpx = px - bx, bpy = py - by, bpz = pz - bz;
    float d3 = abx * bpx + aby * bpy + abz * bpz;
    float d4 = acx * bpx + acy * bpy + acz * bpz;
    float cpx = px - cx, cpy = py - cy, cpz = pz - cz;
    float d5 = abx * cpx + aby * cpy + abz * cpz;
    float d6 = acx * cpx + acy * cpy + acz * cpz;
    float va = d3 * d6 - d5 * d4;
    float vb = d5 * d2 - d1 * d6;
    float vc = d1 * d4 - d3 * d2;
    float den = va + vb + vc;
    den = (fabsf(den) > eps) ? den : 1.0f;
    float wb = vb / den, wc = vc / den;
    float clx = ax + abx * wb + acx * wc;
    float cly = ay + aby * wb + acy * wc;
    float clz = az + abz * wb + acz * wc;
    float tabden = (fabsf(d1 - d3) > eps) ? (d1 - d3) : 1.0f;
    float tab = clamp01(d1 / tabden);
    float tacden = (fabsf(d2 - d6) > eps) ? (d2 - d6) : 1.0f;
    float tac = clamp01(d2 / tacden);
    float numbc = d4 - d3;
    float denbc = numbc + (d5 - d6);
    denbc = (fabsf(denbc) > eps) ? denbc : 1.0f;
    float tbc = clamp01(numbc / denbc);
    if (va <= 0.f && numbc >= 0.f && (d5 - d6) >= 0.f) {
        clx = bx + (cx - bx) * tbc; cly = by + (cy - by) * tbc; clz = bz + (cz - bz) * tbc;
    }
    if (vb <= 0.f && d2 >= 0.f && d6 <= 0.f) {
        clx = ax + acx * tac; cly = ay + acy * tac; clz = az + acz * tac;
    }
    if (vc <= 0.f && d1 >= 0.f && d3 <= 0.f) {
        clx = ax + abx * tab; cly = ay + aby * tab; clz = az + abz * tab;
    }
    if (d6 >= 0.f && d5 <= d6) { clx = cx; cly = cy; clz = cz; }
    if (d3 >= 0.f && d4 <= d3) { clx = bx; cly = by; clz = bz; }
    if (d1 <= 0.f && d2 <= 0.f) { clx = ax; cly = ay; clz = az; }
    float dx = px - clx, dy = py - cly, dz = pz - clz;
    return dx * dx + dy * dy + dz * dz;
}

// ---------------- pcl: dual min-reduction over 2500x8000 ------------------
#define FT 128
#define PT 625
__global__ void __launch_bounds__(FT) k_pcl(const int* __restrict__ faces,
                                            const float* __restrict__ points) {
    int view = blockIdx.z;
    int f = blockIdx.x * FT + threadIdx.x;
    int p0 = blockIdx.y * PT;
    int tid = threadIdx.x, lane = tid & 31, warp = tid >> 5;
    __shared__ float s_wmin[4][PT];

    float ax, ay, az, bx, by, bz, cx, cy, cz;
    {
        int ff = (f < NF) ? f : 0;
        int i0 = __ldg(&faces[3 * ff]);
        int i1 = __ldg(&faces[3 * ff + 1]);
        int i2 = __ldg(&faces[3 * ff + 2]);
        const float* vb = g_verts + view * NV * 3;
        ax = vb[3 * i0]; ay = vb[3 * i0 + 1]; az = vb[3 * i0 + 2];
        bx = vb[3 * i1]; by = vb[3 * i1 + 1]; bz = vb[3 * i1 + 2];
        cx = vb[3 * i2]; cy = vb[3 * i2 + 1]; cz = vb[3 * i2 + 2];
    }
    float fm = 1e30f;
    const float* pp = points + (size_t)(view * NP + p0) * 3;
    for (int i = 0; i < PT; i++) {
        float px = __ldg(&pp[3 * i]);
        float py = __ldg(&pp[3 * i + 1]);
        float pz = __ldg(&pp[3 * i + 2]);
        float d = ptri_sqdist(px, py, pz, ax, ay, az, bx, by, bz, cx, cy, cz);
        if (f >= NF) d = 1e30f; else fm = fminf(fm, d);
        float m = d;
        #pragma unroll
        for (int o = 16; o; o >>= 1) m = fminf(m, __shfl_xor_sync(0xffffffffu, m, o));
        if (lane == 0) s_wmin[warp][i] = m;
    }
    __syncthreads();
    for (int i = tid; i < PT; i += FT) {
        float m = fminf(fminf(s_wmin[0][i], s_wmin[1][i]),
                        fminf(s_wmin[2][i], s_wmin[3][i]));
        atomicMin(&g_minpt[view * NP + p0 + i], __float_as_uint(m));
    }
    if (f < NF) atomicMin(&g_facemin[view * NF + f], __float_as_uint(fm));
}

// ---------------- raster: tiled, bbox-culled soft rasterization ----------
__global__ void __launch_bounds__(256) k_raster(const float* __restrict__ masks,
                                                float* __restrict__ out) {
    int view = blockIdx.y;
    int tile = blockIdx.x;                 // 0..63 (8x8 grid of 16x16 tiles)
    int tx0 = (tile & 7) * 16, ty0 = (tile >> 3) * 16;
    int tid = threadIdx.x;
    int px = tx0 + (tid & 15), py = ty0 + (tid >> 4);
    float qx = 1.0f - (2.0f * px + 1.0f) / 128.0f;
    float qy = 1.0f - (2.0f * py + 1.0f) / 128.0f;
    // pixel-center rect of this tile (x decreasing with column index)
    float tminx = 1.0f - (2.0f * (tx0 + 15) + 1.0f) / 128.0f;
    float tmaxx = 1.0f - (2.0f * tx0 + 1.0f) / 128.0f;
    float tminy = 1.0f - (2.0f * (ty0 + 15) + 1.0f) / 128.0f;
    float tmaxy = 1.0f - (2.0f * ty0 + 1.0f) / 128.0f;

    __shared__ int s_list[256];
    __shared__ int s_wc[8];
    __shared__ int s_woff[8];
    __shared__ int s_tot;

    const float4* bb_base = g_bbox + view * NF;
    const float4* fr_base = g_frec + (size_t)view * NF * 4;
    int lane = tid & 31, warp = tid >> 5;
    float acc = 0.0f;

    for (int base = 0; base < NF; base += 256) {
        int f = base + tid;
        bool ov = false;
        if (f < NF) {
            float4 bb = __ldg(&bb_base[f]);
            ov = (bb.x - RPAD <= tmaxx) && (bb.z + RPAD >= tminx) &&
                 (bb.y - RPAD <= tmaxy) && (bb.w + RPAD >= tminy);
        }
        unsigned bal = __ballot_sync(0xffffffffu, ov);
        if (lane == 0) s_wc[warp] = __popc(bal);
        __syncthreads();
        if (tid == 0) {
            int s = 0;
            for (int w = 0; w < 8; w++) { s_woff[w] = s; s += s_wc[w]; }
            s_tot = s;
        }
        __syncthreads();
        if (ov) {
            int pos = s_woff[warp] + __popc(bal & ((1u << lane) - 1u));
            s_list[pos] = f;
        }
        __syncthreads();
        int M = s_tot;
        for (int j = 0; j < M; j++) {
            int fi = s_list[j];
            float4 r0 = __ldg(&fr_base[fi * 4 + 0]);
            float4 r1 = __ldg(&fr_base[fi * 4 + 1]);
            float4 r2 = __ldg(&fr_base[fi * 4 + 2]);
            float4 r3 = __ldg(&fr_base[fi * 4 + 3]);
            float pax = qx - r0.x, pay = qy - r0.y;
            float pbx = qx - r0.z, pby = qy - r0.w;
            float pcx = qx - r1.x, pcy = qy - r1.y;
            float e1x = r1.z, e1y = r1.w;
            float e2x = r2.x, e2y = r2.y;
            float e3x = r2.z, e3y = r2.w;
            float t1 = clamp01((pax * e1x + pay * e1y) * r3.x);
            float dx = pax - t1 * e1x, dy = pay - t1 * e1y;
            float dd = dx * dx + dy * dy;
            float t2 = clamp01((pbx * e2x + pby * e2y) * r3.y);
            dx = pbx - t2 * e2x; dy = pby - t2 * e2y;
            dd = fminf(dd, dx * dx + dy * dy);
            float t3 = clamp01((pcx * e3x + pcy * e3y) * r3.z);
            dx = pcx - t3 * e3x; dy = pcy - t3 * e3y;
            dd = fminf(dd, dx * dx + dy * dy);
            float s1 = e1x * pay - e1y * pax;
            float s2 = e2x * pby - e2y * pbx;
            float s3 = e3x * pcy - e3y * pcx;
            bool inside = (s1 >= 0.f && s2 >= 0.f && s3 >= 0.f) ||
                          (s1 <= 0.f && s2 <= 0.f && s3 <= 0.f);
            float d = inside ? -dd : dd;
            if (d < BLUR_F) {
                float ex = expf(d * INV_SIGMA);
                float prob = 1.0f / (1.0f + ex);
                prob = fminf(prob, CLIPMAX);
                acc += log1pf(-prob);
            }
        }
        __syncthreads();
    }

    float alpha = 1.0f - expf(acc);
    int pix = py * WW + px;
    out[OFF_ALPHA + view * HH * WW + pix] = alpha;
    float m = masks[view * HH * WW + pix];
    float diff = alpha - m;
    __shared__ float s_red[256];
    s_red[tid] = diff * diff;
    __syncthreads();
    for (int s = 128; s > 0; s >>= 1) {
        if (tid < s) s_red[tid] += s_red[tid + s];
        __syncthreads();
    }
    if (tid == 0) g_msk_part[view * 64 + tile] = s_red[0];
}

// ---------------- final deterministic reductions -------------------------
__global__ void __launch_bounds__(256) k_final(float* __restrict__ out) {
    __shared__ float s[256];
    int tid = threadIdx.x;

    float a = 0.f;
    for (int i = tid; i < VIEWS * NP; i += 256) a += __uint_as_float(g_minpt[i]);
    s[tid] = a; __syncthreads();
    for (int st = 128; st > 0; st >>= 1) { if (tid < st) s[tid] += s[tid + st]; __syncthreads(); }
    float summin = s[0]; __syncthreads();

    float b = 0.f;
    for (int i = tid; i < VIEWS * NF; i += 256) b += __uint_as_float(g_facemin[i]);
    s[tid] = b; __syncthreads();
    for (int st = 128; st > 0; st >>= 1) { if (tid < st) s[tid] += s[tid + st]; __syncthreads(); }
    float sumface = s[0]; __syncthreads();

    float c = 0.f;
    for (int i = tid; i < VIEWS * 64; i += 256) c += g_msk_part[i];
    s[tid] = c; __syncthreads();
    for (int st = 128; st > 0; st >>= 1) { if (tid < st) s[tid] += s[tid + st]; __syncthreads(); }
    float sumsse = s[0];

    if (tid == 0) {
        out[OFF_PCL] = summin / (float)(VIEWS * NP) + sumface / (float)(VIEWS * NF);
        out[OFF_MASK] = sumsse / (float)(VIEWS * HH * WW);
    }
}

// ---------------- launch -------------------------------------------------
extern "C" void kernel_launch(void* const* d_in, const int* in_sizes, int n_in,
                              void* d_out, int out_size) {
    const float* poses = (const float*)d_in[0];
    const float* ident = (const float*)d_in[1];
    const float* expr  = (const float*)d_in[2];
    const float* ts    = (const float*)d_in[3];
    const float* points = (const float*)d_in[4];
    const float* masks  = (const float*)d_in[5];
    const float* tmpl   = (const float*)d_in[6];
    const float* sb     = (const float*)d_in[7];
    const float* eb     = (const float*)d_in[8];
    const float* pb     = (const float*)d_in[9];
    const int*   faces  = (const int*)d_in[10];
    const float* fov    = (const float*)d_in[11];
    float* out = (float*)d_out;

    k_init<<<(VIEWS * NF + 255) / 256, 256>>>();
    k_verts<<<(NV + 127) / 128, 128>>>(poses, ident, expr, ts, tmpl, sb, eb, pb, fov, out);
    k_faceprep<<<(VIEWS * NF + 255) / 256, 256>>>(faces);
    {
        dim3 grid((NF + FT - 1) / FT, NP / PT, VIEWS);
        k_pcl<<<grid, FT>>>(faces, points);
    }
    {
        dim3 grid(64, VIEWS);
        k_raster<<<grid, 256>>>(masks, out);
    }
    k_final<<<1, 256>>>(out);
}